// round 13
// baseline (speedup 1.0000x reference)
#include <cuda_runtime.h>
#include <stdint.h>
#include <math.h>

#define BB 32
#define TT 2048
#define FF 128
#define UU 256
#define U3 768
#define NF 20

#define CLUSTER 8
#define NB 4              // batches per cluster
#define GRU_THREADS 192   // (col in 0..95) x (k-half in 0..1)

// ---------------- scratch (device globals: allocation-free) ----------------
__device__ float g_xw_f[(size_t)BB * TT * U3];   // 201 MB
__device__ float g_xw_b[(size_t)BB * TT * U3];   // 201 MB
__device__ float g_h0[(size_t)BB * TT * 2 * UU]; // 134 MB
__device__ float g_h1[(size_t)BB * TT * 2 * UU]; // 134 MB

// ---------------- f32x2 packed-math helpers ----------------
__device__ __forceinline__ unsigned long long fma2(unsigned long long a,
                                                   unsigned long long b,
                                                   unsigned long long c) {
    unsigned long long d;
    asm("fma.rn.f32x2 %0, %1, %2, %3;" : "=l"(d) : "l"(a), "l"(b), "l"(c));
    return d;
}
__device__ __forceinline__ unsigned long long pack2(float x, float y) {
    unsigned long long u;
    asm("mov.b64 %0, {%1, %2};" : "=l"(u) : "f"(x), "f"(y));
    return u;
}
__device__ __forceinline__ float2 u2f(unsigned long long u) {
    float2 f;
    asm("mov.b64 {%0, %1}, %2;" : "=f"(f.x), "=f"(f.y) : "l"(u));
    return f;
}
__device__ __forceinline__ float sigmoidf(float x) {
    return 1.0f / (1.0f + expf(-x));
}

// ---------------- GEMM + bias: C[M,N] = A[M,K] @ W[K,N] + bias[N] ----------------
// BM=BN=128, BK=8, 256 threads, 8x8 per thread (as 4 row-pairs via f32x2)
__global__ void __launch_bounds__(256) gemm_bias_kernel(
    const float* __restrict__ A, const float* __restrict__ W,
    const float* __restrict__ bias, float* __restrict__ C,
    int M, int N, int K) {
    __shared__ float As[8][128];
    __shared__ float Bs[8][128];
    const int tid = threadIdx.x;
    const int bm = blockIdx.y * 128;
    const int bn = blockIdx.x * 128;
    const int tx = tid & 15, ty = tid >> 4;

    const int arow = tid >> 1;          // 0..127
    const int acol = (tid & 1) * 4;     // 0 or 4
    const int wrow = tid >> 5;          // 0..7
    const int wcol = (tid & 31) * 4;    // 0..124

    const float* Aptr = A + (size_t)(bm + arow) * K + acol;
    const float* Wptr = W + (size_t)wrow * N + bn + wcol;

    unsigned long long acc[4][8];
#pragma unroll
    for (int p = 0; p < 4; ++p)
#pragma unroll
        for (int c = 0; c < 8; ++c) acc[p][c] = 0ull;

    for (int kt = 0; kt < K; kt += 8) {
        float4 a4 = *reinterpret_cast<const float4*>(Aptr + kt);
        float4 w4 = *reinterpret_cast<const float4*>(Wptr + (size_t)kt * N);
        As[acol + 0][arow] = a4.x;
        As[acol + 1][arow] = a4.y;
        As[acol + 2][arow] = a4.z;
        As[acol + 3][arow] = a4.w;
        *reinterpret_cast<float4*>(&Bs[wrow][wcol]) = w4;
        __syncthreads();
#pragma unroll
        for (int k = 0; k < 8; ++k) {
            const unsigned long long* a2 =
                reinterpret_cast<const unsigned long long*>(&As[k][ty * 8]);
            float4 b0 = *reinterpret_cast<const float4*>(&Bs[k][tx * 8]);
            float4 b1 = *reinterpret_cast<const float4*>(&Bs[k][tx * 8 + 4]);
            unsigned long long a20 = a2[0], a21 = a2[1], a22 = a2[2], a23 = a2[3];
            unsigned long long bb[8];
            bb[0] = pack2(b0.x, b0.x); bb[1] = pack2(b0.y, b0.y);
            bb[2] = pack2(b0.z, b0.z); bb[3] = pack2(b0.w, b0.w);
            bb[4] = pack2(b1.x, b1.x); bb[5] = pack2(b1.y, b1.y);
            bb[6] = pack2(b1.z, b1.z); bb[7] = pack2(b1.w, b1.w);
#pragma unroll
            for (int c = 0; c < 8; ++c) {
                acc[0][c] = fma2(a20, bb[c], acc[0][c]);
                acc[1][c] = fma2(a21, bb[c], acc[1][c]);
                acc[2][c] = fma2(a22, bb[c], acc[2][c]);
                acc[3][c] = fma2(a23, bb[c], acc[3][c]);
            }
        }
        __syncthreads();
    }

    float bv[8];
#pragma unroll
    for (int c = 0; c < 8; ++c) bv[c] = bias[bn + tx * 8 + c];
#pragma unroll
    for (int p = 0; p < 4; ++p) {
        float r0[8], r1[8];
#pragma unroll
        for (int c = 0; c < 8; ++c) {
            float2 v = u2f(acc[p][c]);
            r0[c] = v.x + bv[c];
            r1[c] = v.y + bv[c];
        }
        size_t row0 = (size_t)(bm + ty * 8 + 2 * p) * N + bn + tx * 8;
        size_t row1 = row0 + N;
        *reinterpret_cast<float4*>(&C[row0])     = make_float4(r0[0], r0[1], r0[2], r0[3]);
        *reinterpret_cast<float4*>(&C[row0 + 4]) = make_float4(r0[4], r0[5], r0[6], r0[7]);
        *reinterpret_cast<float4*>(&C[row1])     = make_float4(r1[0], r1[1], r1[2], r1[3]);
        *reinterpret_cast<float4*>(&C[row1 + 4]) = make_float4(r1[4], r1[5], r1[6], r1[7]);
    }
}

// ---------------- clustered GRU recurrence (R register-resident) ----------------
// Grid = 128 CTAs, cluster of 8. cid = blockIdx.x>>3 in 0..15:
//   dir = cid>>3 (0 fwd, 1 bwd), grp = cid&7 -> batches [grp*4, grp*4+4).
// CTA rank c owns units [c*32, c*32+32) for all 3 gates (96 columns of R).
// Thread (half, col) holds its 128-float R slice IN REGISTERS for all steps.
// h (256 x 4 batches) double-buffered in every CTA's SMEM via DSMEM stores.
//
// SMEM float layout:
//   sh  [2 parity][NB][256]     : 2048 floats (8 KB)
//   sp  [96 col][2 half][NB]    : 768 floats (3 KB)
#define SH_FLOATS  (2 * NB * 256)
#define SP_FLOATS  (96 * 2 * NB)
#define GRU_SMEM_BYTES ((SH_FLOATS + SP_FLOATS) * 4)

__global__ void __launch_bounds__(GRU_THREADS, 1) __cluster_dims__(CLUSTER, 1, 1)
gru_cluster_kernel(const float* __restrict__ xwF, const float* __restrict__ xwB,
                   const float* __restrict__ rkF, const float* __restrict__ rkB,
                   const float* __restrict__ b1F, const float* __restrict__ b1B,
                   float* __restrict__ out) {
    extern __shared__ float smem[];
    float* sh = smem;
    float* sp = smem + SH_FLOATS;

    const int tid = threadIdx.x;
    unsigned int rank;
    asm("mov.u32 %0, %%cluster_ctarank;" : "=r"(rank));
    const int cid = blockIdx.x >> 3;
    const int dir = cid >> 3;
    const int grp = cid & 7;
    const float* __restrict__ xw = dir ? xwB : xwF;
    const float* __restrict__ rk = dir ? rkB : rkF;
    const float* __restrict__ b1 = dir ? b1B : b1F;

    const int half = tid / 96;
    const int col  = tid % 96;
    const int gate = col >> 5;               // 0,1,2
    const int cg   = gate * UU + (int)rank * 32 + (col & 31);  // global R column

    // ---- load this thread's 128-float R slice into registers (one time) ----
    // rk is k-major [256][768]; thread covers k in [half*128, half*128+128).
    ulonglong2 Rreg[32];
    {
        const float* base = rk + (size_t)(half * 128) * U3 + cg;
#pragma unroll
        for (int kk = 0; kk < 32; ++kk) {
            float v0 = __ldg(base + (size_t)(4 * kk + 0) * U3);
            float v1 = __ldg(base + (size_t)(4 * kk + 1) * U3);
            float v2 = __ldg(base + (size_t)(4 * kk + 2) * U3);
            float v3 = __ldg(base + (size_t)(4 * kk + 3) * U3);
            Rreg[kk].x = pack2(v0, v1);
            Rreg[kk].y = pack2(v2, v3);
        }
    }

    for (int i = tid; i < SH_FLOATS; i += GRU_THREADS) sh[i] = 0.0f;
    __syncthreads();
    // all CTAs' h buffers zeroed before any peer can write into them
    asm volatile("barrier.cluster.arrive.aligned;" ::: "memory");
    asm volatile("barrier.cluster.wait.aligned;" ::: "memory");

    const int u = tid & 31;        // combine threads (tid<128)
    const int b = tid >> 5;        // combine threads: batch 0..3
    const int idxu = (int)rank * 32 + u;

    float bz = 0.f, br = 0.f, bh = 0.f;
    if (tid < 128) {
        bz = b1[idxu];
        br = b1[UU + idxu];
        bh = b1[2 * UU + idxu];
    }
    const size_t browT = (size_t)(grp * NB + b) * TT;
    float hprev = 0.0f;

    unsigned int smem_u32;
    asm("{ .reg .u64 t; cvta.to.shared.u64 t, %1; cvt.u32.u64 %0, t; }"
        : "=r"(smem_u32) : "l"(smem));
    const unsigned int hsBase = smem_u32;   // sh at offset 0

    for (int s = 0; s < TT; ++s) {
        const int t = dir ? (TT - 1 - s) : s;
        const int p = s & 1;

        // x-projection loads for this step (latency hidden behind dot loop)
        float xz = 0.f, xr = 0.f, xh = 0.f;
        if (tid < 128) {
            const float* xrow = xw + (browT + t) * (size_t)U3;
            xz = __ldg(xrow + idxu);
            xr = __ldg(xrow + UU + idxu);
            xh = __ldg(xrow + 2 * UU + idxu);
        }

        // dot products: acc_b = sum_k R[col][k] * h[b][k] over this thread's k-half
        const ulonglong2* __restrict__ Hp =
            reinterpret_cast<const ulonglong2*>(sh) + p * NB * 64 + half * 32;
        unsigned long long a0 = 0, a1 = 0, a2 = 0, a3 = 0;
#pragma unroll
        for (int kk = 0; kk < 32; ++kk) {
            ulonglong2 r  = Rreg[kk];
            ulonglong2 h0 = Hp[kk];
            ulonglong2 h1 = Hp[64 + kk];
            ulonglong2 h2 = Hp[128 + kk];
            ulonglong2 h3 = Hp[192 + kk];
            a0 = fma2(r.x, h0.x, a0); a0 = fma2(r.y, h0.y, a0);
            a1 = fma2(r.x, h1.x, a1); a1 = fma2(r.y, h1.y, a1);
            a2 = fma2(r.x, h2.x, a2); a2 = fma2(r.y, h2.y, a2);
            a3 = fma2(r.x, h3.x, a3); a3 = fma2(r.y, h3.y, a3);
        }
        float2 v;
        v = u2f(a0); sp[(col * 2 + half) * NB + 0] = v.x + v.y;
        v = u2f(a1); sp[(col * 2 + half) * NB + 1] = v.x + v.y;
        v = u2f(a2); sp[(col * 2 + half) * NB + 2] = v.x + v.y;
        v = u2f(a3); sp[(col * 2 + half) * NB + 3] = v.x + v.y;
        __syncthreads();

        if (tid < 128) {
            float dz = sp[((0 * 32 + u) * 2 + 0) * NB + b] + sp[((0 * 32 + u) * 2 + 1) * NB + b];
            float dr = sp[((1 * 32 + u) * 2 + 0) * NB + b] + sp[((1 * 32 + u) * 2 + 1) * NB + b];
            float dh = sp[((2 * 32 + u) * 2 + 0) * NB + b] + sp[((2 * 32 + u) * 2 + 1) * NB + b];
            float z  = sigmoidf(xz + dz + bz);
            float r  = sigmoidf(xr + dr + br);
            float hh = fmaxf(xh + r * (dh + bh), 0.0f);
            float hn = z * hprev + (1.0f - z) * hh;
            hprev = hn;

            // broadcast h_new to all 8 CTAs' sh[(p^1)][b][idxu]
            unsigned int myaddr = hsBase +
                (((unsigned int)(((p ^ 1) * NB + b) * 256 + idxu)) << 2);
#pragma unroll
            for (int rr = 0; rr < CLUSTER; ++rr) {
                unsigned int ra;
                asm("mapa.shared::cluster.u32 %0, %1, %2;"
                    : "=r"(ra) : "r"(myaddr), "r"(rr));
                asm volatile("st.shared::cluster.f32 [%0], %1;"
                             :: "r"(ra), "f"(hn));
            }
            out[(browT + t) * (size_t)(2 * UU) + dir * UU + idxu] = hn;
        }
        // release our h writes / acquire peers' h writes for next step
        asm volatile("barrier.cluster.arrive.aligned;" ::: "memory");
        asm volatile("barrier.cluster.wait.aligned;" ::: "memory");
    }
}

// ---------------- dense + softmax ----------------
__global__ void __launch_bounds__(128) dense_softmax_kernel(
    const float* __restrict__ H, const float* __restrict__ Wd,
    const float* __restrict__ bd, float* __restrict__ out) {
    __shared__ float sW[2 * UU * NF];
    __shared__ float sb[NF];
    const int tid = threadIdx.x;
    for (int idx = tid; idx < 2 * UU * NF; idx += 128) sW[idx] = Wd[idx];
    if (tid < NF) sb[tid] = bd[tid];
    __syncthreads();

    const int lane = tid & 31, warp = tid >> 5;
    const int lane2 = (lane < NF) ? lane : 0;
    const size_t row0 = (size_t)blockIdx.x * 64 + warp * 16;

    for (int rr = 0; rr < 16; ++rr) {
        const size_t row = row0 + rr;
        const float* h = H + row * (size_t)(2 * UU);
        float acc = sb[lane2];
#pragma unroll 4
        for (int k = 0; k < 2 * UU; k += 4) {
            float4 h4 = *reinterpret_cast<const float4*>(h + k);
            acc += h4.x * sW[(k + 0) * NF + lane2];
            acc += h4.y * sW[(k + 1) * NF + lane2];
            acc += h4.z * sW[(k + 2) * NF + lane2];
            acc += h4.w * sW[(k + 3) * NF + lane2];
        }
        float m = (lane < NF) ? acc : -3.4e38f;
        for (int o = 16; o; o >>= 1) m = fmaxf(m, __shfl_xor_sync(0xFFFFFFFFu, m, o));
        float e = (lane < NF) ? expf(acc - m) : 0.0f;
        float ssum = e;
        for (int o = 16; o; o >>= 1) ssum += __shfl_xor_sync(0xFFFFFFFFu, ssum, o);
        if (lane < NF) out[row * NF + lane] = e / ssum;
    }
}

// ---------------- launch ----------------
extern "C" void kernel_launch(void* const* d_in, const int* in_sizes, int n_in,
                              void* d_out, int out_size) {
    const float* x    = (const float*)d_in[0];
    const float* k0f  = (const float*)d_in[1];
    const float* rk0f = (const float*)d_in[2];
    const float* b0f  = (const float*)d_in[3];
    const float* k0b  = (const float*)d_in[4];
    const float* rk0b = (const float*)d_in[5];
    const float* b0b  = (const float*)d_in[6];
    const float* k1f  = (const float*)d_in[7];
    const float* rk1f = (const float*)d_in[8];
    const float* b1f  = (const float*)d_in[9];
    const float* k1b  = (const float*)d_in[10];
    const float* rk1b = (const float*)d_in[11];
    const float* b1b  = (const float*)d_in[12];
    const float* Wd   = (const float*)d_in[13];
    const float* bd   = (const float*)d_in[14];
    float* out = (float*)d_out;

    float *xwf, *xwb, *h0, *h1;
    cudaGetSymbolAddress((void**)&xwf, g_xw_f);
    cudaGetSymbolAddress((void**)&xwb, g_xw_b);
    cudaGetSymbolAddress((void**)&h0, g_h0);
    cudaGetSymbolAddress((void**)&h1, g_h1);

    cudaFuncSetAttribute(gru_cluster_kernel,
                         cudaFuncAttributeMaxDynamicSharedMemorySize,
                         GRU_SMEM_BYTES);

    dim3 gg(U3 / 128, (BB * TT) / 128);  // (6, 512)

    // layer 0 input projections (bias row 0 folded in)
    gemm_bias_kernel<<<gg, 256>>>(x, k0f, b0f, xwf, BB * TT, U3, FF);
    gemm_bias_kernel<<<gg, 256>>>(x, k0b, b0b, xwb, BB * TT, U3, FF);
    // layer 0 recurrence (fwd + bwd, clustered) -> h0 [B,T,512]
    gru_cluster_kernel<<<128, GRU_THREADS, GRU_SMEM_BYTES>>>(
        xwf, xwb, rk0f, rk0b, b0f + U3, b0b + U3, h0);

    // layer 1 input projections (reuse xw buffers)
    gemm_bias_kernel<<<gg, 256>>>(h0, k1f, b1f, xwf, BB * TT, U3, 2 * UU);
    gemm_bias_kernel<<<gg, 256>>>(h0, k1b, b1b, xwb, BB * TT, U3, 2 * UU);
    // layer 1 recurrence -> h1 [B,T,512]
    gru_cluster_kernel<<<128, GRU_THREADS, GRU_SMEM_BYTES>>>(
        xwf, xwb, rk1f, rk1b, b1f + U3, b1b + U3, h1);

    // dense softmax head
    dense_softmax_kernel<<<(BB * TT) / 64, 128>>>(h1, Wd, bd, out);
}

// round 14
// speedup vs baseline: 1.0039x; 1.0039x over previous
#include <cuda_runtime.h>
#include <stdint.h>
#include <math.h>

#define BB 32
#define TT 2048
#define FF 128
#define UU 256
#define U3 768
#define NF 20

#define CLUSTER 8
#define NB 4              // batches per cluster
#define GRU_THREADS 192   // (col in 0..95) x (k-half in 0..1)

// ---------------- scratch (device globals: allocation-free) ----------------
__device__ float g_xw_f[(size_t)BB * TT * U3];   // 201 MB
__device__ float g_xw_b[(size_t)BB * TT * U3];   // 201 MB
__device__ float g_h0[(size_t)BB * TT * 2 * UU]; // 134 MB
__device__ float g_h1[(size_t)BB * TT * 2 * UU]; // 134 MB

// ---------------- f32x2 packed-math helpers ----------------
__device__ __forceinline__ unsigned long long fma2(unsigned long long a,
                                                   unsigned long long b,
                                                   unsigned long long c) {
    unsigned long long d;
    asm("fma.rn.f32x2 %0, %1, %2, %3;" : "=l"(d) : "l"(a), "l"(b), "l"(c));
    return d;
}
__device__ __forceinline__ unsigned long long pack2(float x, float y) {
    unsigned long long u;
    asm("mov.b64 %0, {%1, %2};" : "=l"(u) : "f"(x), "f"(y));
    return u;
}
__device__ __forceinline__ float2 u2f(unsigned long long u) {
    float2 f;
    asm("mov.b64 {%0, %1}, %2;" : "=f"(f.x), "=f"(f.y) : "l"(u));
    return f;
}
__device__ __forceinline__ float sigmoidf(float x) {
    return 1.0f / (1.0f + expf(-x));
}

// ---------------- GEMM + bias: C[M,N] = A[M,K] @ W[K,N] + bias[N] ----------------
// BM=BN=128, BK=8, 256 threads, 8x8 per thread (as 4 row-pairs via f32x2)
__global__ void __launch_bounds__(256) gemm_bias_kernel(
    const float* __restrict__ A, const float* __restrict__ W,
    const float* __restrict__ bias, float* __restrict__ C,
    int M, int N, int K) {
    __shared__ float As[8][128];
    __shared__ float Bs[8][128];
    const int tid = threadIdx.x;
    const int bm = blockIdx.y * 128;
    const int bn = blockIdx.x * 128;
    const int tx = tid & 15, ty = tid >> 4;

    const int arow = tid >> 1;          // 0..127
    const int acol = (tid & 1) * 4;     // 0 or 4
    const int wrow = tid >> 5;          // 0..7
    const int wcol = (tid & 31) * 4;    // 0..124

    const float* Aptr = A + (size_t)(bm + arow) * K + acol;
    const float* Wptr = W + (size_t)wrow * N + bn + wcol;

    unsigned long long acc[4][8];
#pragma unroll
    for (int p = 0; p < 4; ++p)
#pragma unroll
        for (int c = 0; c < 8; ++c) acc[p][c] = 0ull;

    for (int kt = 0; kt < K; kt += 8) {
        float4 a4 = *reinterpret_cast<const float4*>(Aptr + kt);
        float4 w4 = *reinterpret_cast<const float4*>(Wptr + (size_t)kt * N);
        As[acol + 0][arow] = a4.x;
        As[acol + 1][arow] = a4.y;
        As[acol + 2][arow] = a4.z;
        As[acol + 3][arow] = a4.w;
        *reinterpret_cast<float4*>(&Bs[wrow][wcol]) = w4;
        __syncthreads();
#pragma unroll
        for (int k = 0; k < 8; ++k) {
            const unsigned long long* a2 =
                reinterpret_cast<const unsigned long long*>(&As[k][ty * 8]);
            float4 b0 = *reinterpret_cast<const float4*>(&Bs[k][tx * 8]);
            float4 b1 = *reinterpret_cast<const float4*>(&Bs[k][tx * 8 + 4]);
            unsigned long long a20 = a2[0], a21 = a2[1], a22 = a2[2], a23 = a2[3];
            unsigned long long bb[8];
            bb[0] = pack2(b0.x, b0.x); bb[1] = pack2(b0.y, b0.y);
            bb[2] = pack2(b0.z, b0.z); bb[3] = pack2(b0.w, b0.w);
            bb[4] = pack2(b1.x, b1.x); bb[5] = pack2(b1.y, b1.y);
            bb[6] = pack2(b1.z, b1.z); bb[7] = pack2(b1.w, b1.w);
#pragma unroll
            for (int c = 0; c < 8; ++c) {
                acc[0][c] = fma2(a20, bb[c], acc[0][c]);
                acc[1][c] = fma2(a21, bb[c], acc[1][c]);
                acc[2][c] = fma2(a22, bb[c], acc[2][c]);
                acc[3][c] = fma2(a23, bb[c], acc[3][c]);
            }
        }
        __syncthreads();
    }

    float bv[8];
#pragma unroll
    for (int c = 0; c < 8; ++c) bv[c] = bias[bn + tx * 8 + c];
#pragma unroll
    for (int p = 0; p < 4; ++p) {
        float r0[8], r1[8];
#pragma unroll
        for (int c = 0; c < 8; ++c) {
            float2 v = u2f(acc[p][c]);
            r0[c] = v.x + bv[c];
            r1[c] = v.y + bv[c];
        }
        size_t row0 = (size_t)(bm + ty * 8 + 2 * p) * N + bn + tx * 8;
        size_t row1 = row0 + N;
        *reinterpret_cast<float4*>(&C[row0])     = make_float4(r0[0], r0[1], r0[2], r0[3]);
        *reinterpret_cast<float4*>(&C[row0 + 4]) = make_float4(r0[4], r0[5], r0[6], r0[7]);
        *reinterpret_cast<float4*>(&C[row1])     = make_float4(r1[0], r1[1], r1[2], r1[3]);
        *reinterpret_cast<float4*>(&C[row1 + 4]) = make_float4(r1[4], r1[5], r1[6], r1[7]);
    }
}

// ---------------- clustered GRU recurrence (R register-resident) ----------------
// Grid = 128 CTAs, cluster of 8. cid = blockIdx.x>>3 in 0..15:
//   dir = cid>>3 (0 fwd, 1 bwd), grp = cid&7 -> batches [grp*4, grp*4+4).
// CTA rank c owns units [c*32, c*32+32) for all 3 gates (96 columns of R).
// Thread (half, col) holds its 128-float R slice IN REGISTERS for all steps.
// h (256 x 4 batches) double-buffered in every CTA's SMEM via DSMEM stores.
//
// SMEM float layout:
//   sh  [2 parity][NB][256]     : 2048 floats (8 KB)
//   sp  [96 col][2 half][NB]    : 768 floats (3 KB)
#define SH_FLOATS  (2 * NB * 256)
#define SP_FLOATS  (96 * 2 * NB)
#define GRU_SMEM_BYTES ((SH_FLOATS + SP_FLOATS) * 4)

__global__ void __launch_bounds__(GRU_THREADS, 1) __cluster_dims__(CLUSTER, 1, 1)
gru_cluster_kernel(const float* __restrict__ xwF, const float* __restrict__ xwB,
                   const float* __restrict__ rkF, const float* __restrict__ rkB,
                   const float* __restrict__ b1F, const float* __restrict__ b1B,
                   float* __restrict__ out) {
    extern __shared__ float smem[];
    float* sh = smem;
    float* sp = smem + SH_FLOATS;

    const int tid = threadIdx.x;
    unsigned int rank;
    asm("mov.u32 %0, %%cluster_ctarank;" : "=r"(rank));
    const int cid = blockIdx.x >> 3;
    const int dir = cid >> 3;
    const int grp = cid & 7;
    const float* __restrict__ xw = dir ? xwB : xwF;
    const float* __restrict__ rk = dir ? rkB : rkF;
    const float* __restrict__ b1 = dir ? b1B : b1F;

    const int half = tid / 96;
    const int col  = tid % 96;
    const int gate = col >> 5;               // 0,1,2
    const int cg   = gate * UU + (int)rank * 32 + (col & 31);  // global R column

    // ---- load this thread's 128-float R slice into registers (one time) ----
    // rk is k-major [256][768]; thread covers k in [half*128, half*128+128).
    ulonglong2 Rreg[32];
    {
        const float* base = rk + (size_t)(half * 128) * U3 + cg;
#pragma unroll
        for (int kk = 0; kk < 32; ++kk) {
            float v0 = __ldg(base + (size_t)(4 * kk + 0) * U3);
            float v1 = __ldg(base + (size_t)(4 * kk + 1) * U3);
            float v2 = __ldg(base + (size_t)(4 * kk + 2) * U3);
            float v3 = __ldg(base + (size_t)(4 * kk + 3) * U3);
            Rreg[kk].x = pack2(v0, v1);
            Rreg[kk].y = pack2(v2, v3);
        }
    }

    for (int i = tid; i < SH_FLOATS; i += GRU_THREADS) sh[i] = 0.0f;
    __syncthreads();
    // all CTAs' h buffers zeroed before any peer can write into them
    asm volatile("barrier.cluster.arrive.aligned;" ::: "memory");
    asm volatile("barrier.cluster.wait.aligned;" ::: "memory");

    const int u = tid & 31;        // combine threads (tid<128)
    const int b = tid >> 5;        // combine threads: batch 0..3
    const int idxu = (int)rank * 32 + u;

    float bz = 0.f, br = 0.f, bh = 0.f;
    if (tid < 128) {
        bz = b1[idxu];
        br = b1[UU + idxu];
        bh = b1[2 * UU + idxu];
    }
    const size_t browT = (size_t)(grp * NB + b) * TT;
    float hprev = 0.0f;

    unsigned int smem_u32;
    asm("{ .reg .u64 t; cvta.to.shared.u64 t, %1; cvt.u32.u64 %0, t; }"
        : "=r"(smem_u32) : "l"(smem));
    const unsigned int hsBase = smem_u32;   // sh at offset 0

    for (int s = 0; s < TT; ++s) {
        const int t = dir ? (TT - 1 - s) : s;
        const int p = s & 1;

        // x-projection loads for this step (latency hidden behind dot loop)
        float xz = 0.f, xr = 0.f, xh = 0.f;
        if (tid < 128) {
            const float* xrow = xw + (browT + t) * (size_t)U3;
            xz = __ldg(xrow + idxu);
            xr = __ldg(xrow + UU + idxu);
            xh = __ldg(xrow + 2 * UU + idxu);
        }

        // dot products: acc_b = sum_k R[col][k] * h[b][k] over this thread's k-half
        const ulonglong2* __restrict__ Hp =
            reinterpret_cast<const ulonglong2*>(sh) + p * NB * 64 + half * 32;
        unsigned long long a0 = 0, a1 = 0, a2 = 0, a3 = 0;
#pragma unroll
        for (int kk = 0; kk < 32; ++kk) {
            ulonglong2 r  = Rreg[kk];
            ulonglong2 h0 = Hp[kk];
            ulonglong2 h1 = Hp[64 + kk];
            ulonglong2 h2 = Hp[128 + kk];
            ulonglong2 h3 = Hp[192 + kk];
            a0 = fma2(r.x, h0.x, a0); a0 = fma2(r.y, h0.y, a0);
            a1 = fma2(r.x, h1.x, a1); a1 = fma2(r.y, h1.y, a1);
            a2 = fma2(r.x, h2.x, a2); a2 = fma2(r.y, h2.y, a2);
            a3 = fma2(r.x, h3.x, a3); a3 = fma2(r.y, h3.y, a3);
        }
        float2 v;
        v = u2f(a0); sp[(col * 2 + half) * NB + 0] = v.x + v.y;
        v = u2f(a1); sp[(col * 2 + half) * NB + 1] = v.x + v.y;
        v = u2f(a2); sp[(col * 2 + half) * NB + 2] = v.x + v.y;
        v = u2f(a3); sp[(col * 2 + half) * NB + 3] = v.x + v.y;
        __syncthreads();

        if (tid < 128) {
            float dz = sp[((0 * 32 + u) * 2 + 0) * NB + b] + sp[((0 * 32 + u) * 2 + 1) * NB + b];
            float dr = sp[((1 * 32 + u) * 2 + 0) * NB + b] + sp[((1 * 32 + u) * 2 + 1) * NB + b];
            float dh = sp[((2 * 32 + u) * 2 + 0) * NB + b] + sp[((2 * 32 + u) * 2 + 1) * NB + b];
            float z  = sigmoidf(xz + dz + bz);
            float r  = sigmoidf(xr + dr + br);
            float hh = fmaxf(xh + r * (dh + bh), 0.0f);
            float hn = z * hprev + (1.0f - z) * hh;
            hprev = hn;

            // broadcast h_new to all 8 CTAs' sh[(p^1)][b][idxu]
            unsigned int myaddr = hsBase +
                (((unsigned int)(((p ^ 1) * NB + b) * 256 + idxu)) << 2);
#pragma unroll
            for (int rr = 0; rr < CLUSTER; ++rr) {
                unsigned int ra;
                asm("mapa.shared::cluster.u32 %0, %1, %2;"
                    : "=r"(ra) : "r"(myaddr), "r"(rr));
                asm volatile("st.shared::cluster.f32 [%0], %1;"
                             :: "r"(ra), "f"(hn));
            }
            out[(browT + t) * (size_t)(2 * UU) + dir * UU + idxu] = hn;
        }
        // release our h writes / acquire peers' h writes for next step
        asm volatile("barrier.cluster.arrive.aligned;" ::: "memory");
        asm volatile("barrier.cluster.wait.aligned;" ::: "memory");
    }
}

// ---------------- dense + softmax ----------------
__global__ void __launch_bounds__(128) dense_softmax_kernel(
    const float* __restrict__ H, const float* __restrict__ Wd,
    const float* __restrict__ bd, float* __restrict__ out) {
    __shared__ float sW[2 * UU * NF];
    __shared__ float sb[NF];
    const int tid = threadIdx.x;
    for (int idx = tid; idx < 2 * UU * NF; idx += 128) sW[idx] = Wd[idx];
    if (tid < NF) sb[tid] = bd[tid];
    __syncthreads();

    const int lane = tid & 31, warp = tid >> 5;
    const int lane2 = (lane < NF) ? lane : 0;
    const size_t row0 = (size_t)blockIdx.x * 64 + warp * 16;

    for (int rr = 0; rr < 16; ++rr) {
        const size_t row = row0 + rr;
        const float* h = H + row * (size_t)(2 * UU);
        float acc = sb[lane2];
#pragma unroll 4
        for (int k = 0; k < 2 * UU; k += 4) {
            float4 h4 = *reinterpret_cast<const float4*>(h + k);
            acc += h4.x * sW[(k + 0) * NF + lane2];
            acc += h4.y * sW[(k + 1) * NF + lane2];
            acc += h4.z * sW[(k + 2) * NF + lane2];
            acc += h4.w * sW[(k + 3) * NF + lane2];
        }
        float m = (lane < NF) ? acc : -3.4e38f;
        for (int o = 16; o; o >>= 1) m = fmaxf(m, __shfl_xor_sync(0xFFFFFFFFu, m, o));
        float e = (lane < NF) ? expf(acc - m) : 0.0f;
        float ssum = e;
        for (int o = 16; o; o >>= 1) ssum += __shfl_xor_sync(0xFFFFFFFFu, ssum, o);
        if (lane < NF) out[row * NF + lane] = e / ssum;
    }
}

// ---------------- launch ----------------
extern "C" void kernel_launch(void* const* d_in, const int* in_sizes, int n_in,
                              void* d_out, int out_size) {
    const float* x    = (const float*)d_in[0];
    const float* k0f  = (const float*)d_in[1];
    const float* rk0f = (const float*)d_in[2];
    const float* b0f  = (const float*)d_in[3];
    const float* k0b  = (const float*)d_in[4];
    const float* rk0b = (const float*)d_in[5];
    const float* b0b  = (const float*)d_in[6];
    const float* k1f  = (const float*)d_in[7];
    const float* rk1f = (const float*)d_in[8];
    const float* b1f  = (const float*)d_in[9];
    const float* k1b  = (const float*)d_in[10];
    const float* rk1b = (const float*)d_in[11];
    const float* b1b  = (const float*)d_in[12];
    const float* Wd   = (const float*)d_in[13];
    const float* bd   = (const float*)d_in[14];
    float* out = (float*)d_out;

    float *xwf, *xwb, *h0, *h1;
    cudaGetSymbolAddress((void**)&xwf, g_xw_f);
    cudaGetSymbolAddress((void**)&xwb, g_xw_b);
    cudaGetSymbolAddress((void**)&h0, g_h0);
    cudaGetSymbolAddress((void**)&h1, g_h1);

    cudaFuncSetAttribute(gru_cluster_kernel,
                         cudaFuncAttributeMaxDynamicSharedMemorySize,
                         GRU_SMEM_BYTES);

    dim3 gg(U3 / 128, (BB * TT) / 128);  // (6, 512)

    // layer 0 input projections (bias row 0 folded in)
    gemm_bias_kernel<<<gg, 256>>>(x, k0f, b0f, xwf, BB * TT, U3, FF);
    gemm_bias_kernel<<<gg, 256>>>(x, k0b, b0b, xwb, BB * TT, U3, FF);
    // layer 0 recurrence (fwd + bwd, clustered) -> h0 [B,T,512]
    gru_cluster_kernel<<<128, GRU_THREADS, GRU_SMEM_BYTES>>>(
        xwf, xwb, rk0f, rk0b, b0f + U3, b0b + U3, h0);

    // layer 1 input projections (reuse xw buffers)
    gemm_bias_kernel<<<gg, 256>>>(h0, k1f, b1f, xwf, BB * TT, U3, 2 * UU);
    gemm_bias_kernel<<<gg, 256>>>(h0, k1b, b1b, xwb, BB * TT, U3, 2 * UU);
    // layer 1 recurrence -> h1 [B,T,512]
    gru_cluster_kernel<<<128, GRU_THREADS, GRU_SMEM_BYTES>>>(
        xwf, xwb, rk1f, rk1b, b1f + U3, b1b + U3, h1);

    // dense softmax head
    dense_softmax_kernel<<<(BB * TT) / 64, 128>>>(h1, Wd, bd, out);
}

// round 15
// speedup vs baseline: 1.0140x; 1.0101x over previous
#include <cuda_runtime.h>
#include <stdint.h>
#include <math.h>

#define BB 32
#define TT 2048
#define FF 128
#define UU 256
#define U3 768
#define NF 20

#define CLUSTER 8
#define NB 4              // batches per cluster
#define GRU_THREADS 192   // (col in 0..95) x (k-half in 0..1)

// ---------------- scratch (device globals: allocation-free) ----------------
__device__ float g_xw_f[(size_t)BB * TT * U3];   // 201 MB
__device__ float g_xw_b[(size_t)BB * TT * U3];   // 201 MB
__device__ float g_h0[(size_t)BB * TT * 2 * UU]; // 134 MB
__device__ float g_h1[(size_t)BB * TT * 2 * UU]; // 134 MB

// ---------------- f32x2 packed-math helpers ----------------
__device__ __forceinline__ unsigned long long fma2(unsigned long long a,
                                                   unsigned long long b,
                                                   unsigned long long c) {
    unsigned long long d;
    asm("fma.rn.f32x2 %0, %1, %2, %3;" : "=l"(d) : "l"(a), "l"(b), "l"(c));
    return d;
}
__device__ __forceinline__ unsigned long long pack2(float x, float y) {
    unsigned long long u;
    asm("mov.b64 %0, {%1, %2};" : "=l"(u) : "f"(x), "f"(y));
    return u;
}
__device__ __forceinline__ float2 u2f(unsigned long long u) {
    float2 f;
    asm("mov.b64 {%0, %1}, %2;" : "=f"(f.x), "=f"(f.y) : "l"(u));
    return f;
}
__device__ __forceinline__ float sigmoidf(float x) {
    return 1.0f / (1.0f + expf(-x));
}

// ---------------- GEMM + bias: C[M,N] = A[M,K] @ W[K,N] + bias[N] ----------------
// BM=BN=128, BK=8, 256 threads, 8x8 per thread (as 4 row-pairs via f32x2)
__global__ void __launch_bounds__(256) gemm_bias_kernel(
    const float* __restrict__ A, const float* __restrict__ W,
    const float* __restrict__ bias, float* __restrict__ C,
    int M, int N, int K) {
    __shared__ float As[8][128];
    __shared__ float Bs[8][128];
    const int tid = threadIdx.x;
    const int bm = blockIdx.y * 128;
    const int bn = blockIdx.x * 128;
    const int tx = tid & 15, ty = tid >> 4;

    const int arow = tid >> 1;          // 0..127
    const int acol = (tid & 1) * 4;     // 0 or 4
    const int wrow = tid >> 5;          // 0..7
    const int wcol = (tid & 31) * 4;    // 0..124

    const float* Aptr = A + (size_t)(bm + arow) * K + acol;
    const float* Wptr = W + (size_t)wrow * N + bn + wcol;

    unsigned long long acc[4][8];
#pragma unroll
    for (int p = 0; p < 4; ++p)
#pragma unroll
        for (int c = 0; c < 8; ++c) acc[p][c] = 0ull;

    for (int kt = 0; kt < K; kt += 8) {
        float4 a4 = *reinterpret_cast<const float4*>(Aptr + kt);
        float4 w4 = *reinterpret_cast<const float4*>(Wptr + (size_t)kt * N);
        As[acol + 0][arow] = a4.x;
        As[acol + 1][arow] = a4.y;
        As[acol + 2][arow] = a4.z;
        As[acol + 3][arow] = a4.w;
        *reinterpret_cast<float4*>(&Bs[wrow][wcol]) = w4;
        __syncthreads();
#pragma unroll
        for (int k = 0; k < 8; ++k) {
            const unsigned long long* a2 =
                reinterpret_cast<const unsigned long long*>(&As[k][ty * 8]);
            float4 b0 = *reinterpret_cast<const float4*>(&Bs[k][tx * 8]);
            float4 b1 = *reinterpret_cast<const float4*>(&Bs[k][tx * 8 + 4]);
            unsigned long long a20 = a2[0], a21 = a2[1], a22 = a2[2], a23 = a2[3];
            unsigned long long bb[8];
            bb[0] = pack2(b0.x, b0.x); bb[1] = pack2(b0.y, b0.y);
            bb[2] = pack2(b0.z, b0.z); bb[3] = pack2(b0.w, b0.w);
            bb[4] = pack2(b1.x, b1.x); bb[5] = pack2(b1.y, b1.y);
            bb[6] = pack2(b1.z, b1.z); bb[7] = pack2(b1.w, b1.w);
#pragma unroll
            for (int c = 0; c < 8; ++c) {
                acc[0][c] = fma2(a20, bb[c], acc[0][c]);
                acc[1][c] = fma2(a21, bb[c], acc[1][c]);
                acc[2][c] = fma2(a22, bb[c], acc[2][c]);
                acc[3][c] = fma2(a23, bb[c], acc[3][c]);
            }
        }
        __syncthreads();
    }

    float bv[8];
#pragma unroll
    for (int c = 0; c < 8; ++c) bv[c] = bias[bn + tx * 8 + c];
#pragma unroll
    for (int p = 0; p < 4; ++p) {
        float r0[8], r1[8];
#pragma unroll
        for (int c = 0; c < 8; ++c) {
            float2 v = u2f(acc[p][c]);
            r0[c] = v.x + bv[c];
            r1[c] = v.y + bv[c];
        }
        size_t row0 = (size_t)(bm + ty * 8 + 2 * p) * N + bn + tx * 8;
        size_t row1 = row0 + N;
        *reinterpret_cast<float4*>(&C[row0])     = make_float4(r0[0], r0[1], r0[2], r0[3]);
        *reinterpret_cast<float4*>(&C[row0 + 4]) = make_float4(r0[4], r0[5], r0[6], r0[7]);
        *reinterpret_cast<float4*>(&C[row1])     = make_float4(r1[0], r1[1], r1[2], r1[3]);
        *reinterpret_cast<float4*>(&C[row1 + 4]) = make_float4(r1[4], r1[5], r1[6], r1[7]);
    }
}

// ---------------- clustered GRU recurrence (R register-resident) ----------------
// Grid = 128 CTAs, cluster of 8. cid = blockIdx.x>>3 in 0..15:
//   dir = cid>>3 (0 fwd, 1 bwd), grp = cid&7 -> batches [grp*4, grp*4+4).
// CTA rank c owns units [c*32, c*32+32) for all 3 gates (96 columns of R).
// Thread (half, col) holds its 128-float R slice IN REGISTERS for all steps.
// h (256 x 4 batches) double-buffered in every CTA's SMEM via DSMEM stores.
//
// SMEM float layout:
//   sh  [2 parity][NB][256]     : 2048 floats (8 KB)
//   sp  [96 col][2 half][NB]    : 768 floats (3 KB)
#define SH_FLOATS  (2 * NB * 256)
#define SP_FLOATS  (96 * 2 * NB)
#define GRU_SMEM_BYTES ((SH_FLOATS + SP_FLOATS) * 4)

__global__ void __launch_bounds__(GRU_THREADS, 1) __cluster_dims__(CLUSTER, 1, 1)
gru_cluster_kernel(const float* __restrict__ xwF, const float* __restrict__ xwB,
                   const float* __restrict__ rkF, const float* __restrict__ rkB,
                   const float* __restrict__ b1F, const float* __restrict__ b1B,
                   float* __restrict__ out) {
    extern __shared__ float smem[];
    float* sh = smem;
    float* sp = smem + SH_FLOATS;

    const int tid = threadIdx.x;
    unsigned int rank;
    asm("mov.u32 %0, %%cluster_ctarank;" : "=r"(rank));
    const int cid = blockIdx.x >> 3;
    const int dir = cid >> 3;
    const int grp = cid & 7;
    const float* __restrict__ xw = dir ? xwB : xwF;
    const float* __restrict__ rk = dir ? rkB : rkF;
    const float* __restrict__ b1 = dir ? b1B : b1F;

    const int half = tid / 96;
    const int col  = tid % 96;
    const int gate = col >> 5;               // 0,1,2
    const int cg   = gate * UU + (int)rank * 32 + (col & 31);  // global R column

    // ---- load this thread's 128-float R slice into registers (one time) ----
    // rk is k-major [256][768]; thread covers k in [half*128, half*128+128).
    ulonglong2 Rreg[32];
    {
        const float* base = rk + (size_t)(half * 128) * U3 + cg;
#pragma unroll
        for (int kk = 0; kk < 32; ++kk) {
            float v0 = __ldg(base + (size_t)(4 * kk + 0) * U3);
            float v1 = __ldg(base + (size_t)(4 * kk + 1) * U3);
            float v2 = __ldg(base + (size_t)(4 * kk + 2) * U3);
            float v3 = __ldg(base + (size_t)(4 * kk + 3) * U3);
            Rreg[kk].x = pack2(v0, v1);
            Rreg[kk].y = pack2(v2, v3);
        }
    }

    for (int i = tid; i < SH_FLOATS; i += GRU_THREADS) sh[i] = 0.0f;
    __syncthreads();
    // all CTAs' h buffers zeroed before any peer can write into them
    asm volatile("barrier.cluster.arrive.aligned;" ::: "memory");
    asm volatile("barrier.cluster.wait.aligned;" ::: "memory");

    const int u = tid & 31;        // combine threads (tid<128)
    const int b = tid >> 5;        // combine threads: batch 0..3
    const int idxu = (int)rank * 32 + u;

    float bz = 0.f, br = 0.f, bh = 0.f;
    if (tid < 128) {
        bz = b1[idxu];
        br = b1[UU + idxu];
        bh = b1[2 * UU + idxu];
    }
    const size_t browT = (size_t)(grp * NB + b) * TT;
    float hprev = 0.0f;

    unsigned int smem_u32;
    asm("{ .reg .u64 t; cvta.to.shared.u64 t, %1; cvt.u32.u64 %0, t; }"
        : "=r"(smem_u32) : "l"(smem));
    const unsigned int hsBase = smem_u32;   // sh at offset 0

    for (int s = 0; s < TT; ++s) {
        const int t = dir ? (TT - 1 - s) : s;
        const int p = s & 1;

        // x-projection loads for this step (latency hidden behind dot loop)
        float xz = 0.f, xr = 0.f, xh = 0.f;
        if (tid < 128) {
            const float* xrow = xw + (browT + t) * (size_t)U3;
            xz = __ldg(xrow + idxu);
            xr = __ldg(xrow + UU + idxu);
            xh = __ldg(xrow + 2 * UU + idxu);
        }

        // dot products: acc_b = sum_k R[col][k] * h[b][k] over this thread's k-half
        const ulonglong2* __restrict__ Hp =
            reinterpret_cast<const ulonglong2*>(sh) + p * NB * 64 + half * 32;
        unsigned long long a0 = 0, a1 = 0, a2 = 0, a3 = 0;
#pragma unroll
        for (int kk = 0; kk < 32; ++kk) {
            ulonglong2 r  = Rreg[kk];
            ulonglong2 h0 = Hp[kk];
            ulonglong2 h1 = Hp[64 + kk];
            ulonglong2 h2 = Hp[128 + kk];
            ulonglong2 h3 = Hp[192 + kk];
            a0 = fma2(r.x, h0.x, a0); a0 = fma2(r.y, h0.y, a0);
            a1 = fma2(r.x, h1.x, a1); a1 = fma2(r.y, h1.y, a1);
            a2 = fma2(r.x, h2.x, a2); a2 = fma2(r.y, h2.y, a2);
            a3 = fma2(r.x, h3.x, a3); a3 = fma2(r.y, h3.y, a3);
        }
        float2 v;
        v = u2f(a0); sp[(col * 2 + half) * NB + 0] = v.x + v.y;
        v = u2f(a1); sp[(col * 2 + half) * NB + 1] = v.x + v.y;
        v = u2f(a2); sp[(col * 2 + half) * NB + 2] = v.x + v.y;
        v = u2f(a3); sp[(col * 2 + half) * NB + 3] = v.x + v.y;
        __syncthreads();

        if (tid < 128) {
            float dz = sp[((0 * 32 + u) * 2 + 0) * NB + b] + sp[((0 * 32 + u) * 2 + 1) * NB + b];
            float dr = sp[((1 * 32 + u) * 2 + 0) * NB + b] + sp[((1 * 32 + u) * 2 + 1) * NB + b];
            float dh = sp[((2 * 32 + u) * 2 + 0) * NB + b] + sp[((2 * 32 + u) * 2 + 1) * NB + b];
            float z  = sigmoidf(xz + dz + bz);
            float r  = sigmoidf(xr + dr + br);
            float hh = fmaxf(xh + r * (dh + bh), 0.0f);
            float hn = z * hprev + (1.0f - z) * hh;
            hprev = hn;

            // broadcast h_new to all 8 CTAs' sh[(p^1)][b][idxu]
            unsigned int myaddr = hsBase +
                (((unsigned int)(((p ^ 1) * NB + b) * 256 + idxu)) << 2);
#pragma unroll
            for (int rr = 0; rr < CLUSTER; ++rr) {
                unsigned int ra;
                asm("mapa.shared::cluster.u32 %0, %1, %2;"
                    : "=r"(ra) : "r"(myaddr), "r"(rr));
                asm volatile("st.shared::cluster.f32 [%0], %1;"
                             :: "r"(ra), "f"(hn));
            }
            out[(browT + t) * (size_t)(2 * UU) + dir * UU + idxu] = hn;
        }
        // release our h writes / acquire peers' h writes for next step
        asm volatile("barrier.cluster.arrive.aligned;" ::: "memory");
        asm volatile("barrier.cluster.wait.aligned;" ::: "memory");
    }
}

// ---------------- dense + softmax ----------------
__global__ void __launch_bounds__(128) dense_softmax_kernel(
    const float* __restrict__ H, const float* __restrict__ Wd,
    const float* __restrict__ bd, float* __restrict__ out) {
    __shared__ float sW[2 * UU * NF];
    __shared__ float sb[NF];
    const int tid = threadIdx.x;
    for (int idx = tid; idx < 2 * UU * NF; idx += 128) sW[idx] = Wd[idx];
    if (tid < NF) sb[tid] = bd[tid];
    __syncthreads();

    const int lane = tid & 31, warp = tid >> 5;
    const int lane2 = (lane < NF) ? lane : 0;
    const size_t row0 = (size_t)blockIdx.x * 64 + warp * 16;

    for (int rr = 0; rr < 16; ++rr) {
        const size_t row = row0 + rr;
        const float* h = H + row * (size_t)(2 * UU);
        float acc = sb[lane2];
#pragma unroll 4
        for (int k = 0; k < 2 * UU; k += 4) {
            float4 h4 = *reinterpret_cast<const float4*>(h + k);
            acc += h4.x * sW[(k + 0) * NF + lane2];
            acc += h4.y * sW[(k + 1) * NF + lane2];
            acc += h4.z * sW[(k + 2) * NF + lane2];
            acc += h4.w * sW[(k + 3) * NF + lane2];
        }
        float m = (lane < NF) ? acc : -3.4e38f;
        for (int o = 16; o; o >>= 1) m = fmaxf(m, __shfl_xor_sync(0xFFFFFFFFu, m, o));
        float e = (lane < NF) ? expf(acc - m) : 0.0f;
        float ssum = e;
        for (int o = 16; o; o >>= 1) ssum += __shfl_xor_sync(0xFFFFFFFFu, ssum, o);
        if (lane < NF) out[row * NF + lane] = e / ssum;
    }
}

// ---------------- launch ----------------
extern "C" void kernel_launch(void* const* d_in, const int* in_sizes, int n_in,
                              void* d_out, int out_size) {
    const float* x    = (const float*)d_in[0];
    const float* k0f  = (const float*)d_in[1];
    const float* rk0f = (const float*)d_in[2];
    const float* b0f  = (const float*)d_in[3];
    const float* k0b  = (const float*)d_in[4];
    const float* rk0b = (const float*)d_in[5];
    const float* b0b  = (const float*)d_in[6];
    const float* k1f  = (const float*)d_in[7];
    const float* rk1f = (const float*)d_in[8];
    const float* b1f  = (const float*)d_in[9];
    const float* k1b  = (const float*)d_in[10];
    const float* rk1b = (const float*)d_in[11];
    const float* b1b  = (const float*)d_in[12];
    const float* Wd   = (const float*)d_in[13];
    const float* bd   = (const float*)d_in[14];
    float* out = (float*)d_out;

    float *xwf, *xwb, *h0, *h1;
    cudaGetSymbolAddress((void**)&xwf, g_xw_f);
    cudaGetSymbolAddress((void**)&xwb, g_xw_b);
    cudaGetSymbolAddress((void**)&h0, g_h0);
    cudaGetSymbolAddress((void**)&h1, g_h1);

    cudaFuncSetAttribute(gru_cluster_kernel,
                         cudaFuncAttributeMaxDynamicSharedMemorySize,
                         GRU_SMEM_BYTES);

    dim3 gg(U3 / 128, (BB * TT) / 128);  // (6, 512)

    // layer 0 input projections (bias row 0 folded in)
    gemm_bias_kernel<<<gg, 256>>>(x, k0f, b0f, xwf, BB * TT, U3, FF);
    gemm_bias_kernel<<<gg, 256>>>(x, k0b, b0b, xwb, BB * TT, U3, FF);
    // layer 0 recurrence (fwd + bwd, clustered) -> h0 [B,T,512]
    gru_cluster_kernel<<<128, GRU_THREADS, GRU_SMEM_BYTES>>>(
        xwf, xwb, rk0f, rk0b, b0f + U3, b0b + U3, h0);

    // layer 1 input projections (reuse xw buffers)
    gemm_bias_kernel<<<gg, 256>>>(h0, k1f, b1f, xwf, BB * TT, U3, 2 * UU);
    gemm_bias_kernel<<<gg, 256>>>(h0, k1b, b1b, xwb, BB * TT, U3, 2 * UU);
    // layer 1 recurrence -> h1 [B,T,512]
    gru_cluster_kernel<<<128, GRU_THREADS, GRU_SMEM_BYTES>>>(
        xwf, xwb, rk1f, rk1b, b1f + U3, b1b + U3, h1);

    // dense softmax head
    dense_softmax_kernel<<<(BB * TT) / 64, 128>>>(h1, Wd, bd, out);
}